// round 15
// baseline (speedup 1.0000x reference)
#include <cuda_runtime.h>
#include <cuda_bf16.h>
#include <math_constants.h>
#include <cstdint>

// Problem constants
constexpr int BB = 4;      // batch
constexpr int NN = 4096;   // H*W tokens
constexpr int CH = 256;    // channels

// Attention tiling
constexpr int TQ = 128;    // queries per CTA
constexpr int TK = 64;     // keys per tile
constexpr int NT = NN / TK;
constexpr int ATTN_THREADS = 512;   // 16 warps: 8 q-groups x 2 c-halves

// ---- device scratch (bf16 hi/lo split operands) ----
__device__ __nv_bfloat16 g_q[(size_t)BB * NN * 64];     // [token][qh(32)|ql(32)]
__device__ __nv_bfloat16 g_k[(size_t)BB * NN * 64];     // [token][kh(32)|kl(32)]
__device__ __nv_bfloat16 g_vth[(size_t)BB * 256 * NN];  // [b][channel][token] V hi (transposed)
__device__ __nv_bfloat16 g_vtl[(size_t)BB * 256 * NN];  // V lo (transposed)

// ---- attn smem layout (bytes). ALL planes 144B pitch (ldmatrix conflict-free) ----
constexpr uint32_t OFF_Q   = 0;                    // 128 x 144 = 18432
constexpr uint32_t OFF_K0  = 18432;                // 64 x 144 = 9216
constexpr uint32_t OFF_K1  = OFF_K0 + 9216;
constexpr uint32_t OFF_VH0 = OFF_K1 + 9216;        // 256 x 144 = 36864
constexpr uint32_t OFF_VL0 = OFF_VH0 + 36864;
constexpr uint32_t OFF_VH1 = OFF_VL0 + 36864;
constexpr uint32_t OFF_VL1 = OFF_VH1 + 36864;
constexpr uint32_t SMEM_TOTAL = OFF_VL1 + 36864;   // 184320 B

// ---------------------------------------------------------------------------
// helpers
// ---------------------------------------------------------------------------
union F2U { float2 f; unsigned long long u; };
__device__ __forceinline__ float2 ffma2(float2 a, float2 b, float2 c) {
    F2U A, B, C, D;
    A.f = a; B.f = b; C.f = c;
    asm("fma.rn.f32x2 %0, %1, %2, %3;" : "=l"(D.u) : "l"(A.u), "l"(B.u), "l"(C.u));
    return D.f;
}

__device__ __forceinline__ uint32_t smem_u32(const void* p) {
    return (uint32_t)__cvta_generic_to_shared(const_cast<void*>(p));
}
__device__ __forceinline__ void cpa16(uint32_t dst, const void* src) {
    asm volatile("cp.async.cg.shared.global [%0], [%1], 16;" :: "r"(dst), "l"(src));
}

// mma.sync m16n8k16 row.col bf16 -> f32 accumulate (base sm_80+ PTX)
__device__ __forceinline__ void mma_bf16(float d[4], const uint32_t a[4],
                                         uint32_t b0, uint32_t b1) {
    asm volatile(
        "mma.sync.aligned.m16n8k16.row.col.f32.bf16.bf16.f32 "
        "{%0,%1,%2,%3}, {%4,%5,%6,%7}, {%8,%9}, {%0,%1,%2,%3};"
        : "+f"(d[0]), "+f"(d[1]), "+f"(d[2]), "+f"(d[3])
        : "r"(a[0]), "r"(a[1]), "r"(a[2]), "r"(a[3]), "r"(b0), "r"(b1));
}

// ldmatrix: 4x 8x8 b16 blocks, one per 8-lane address group
__device__ __forceinline__ void ldm_x4(uint32_t addr, uint32_t& r0, uint32_t& r1,
                                       uint32_t& r2, uint32_t& r3) {
    asm volatile("ldmatrix.sync.aligned.m8n8.x4.shared.b16 {%0,%1,%2,%3}, [%4];"
                 : "=r"(r0), "=r"(r1), "=r"(r2), "=r"(r3) : "r"(addr));
}

// split (x, y) into bf16x2 hi + bf16x2 residual-lo
__device__ __forceinline__ void bsplit(float x, float y, uint32_t& hi, uint32_t& lo) {
    __nv_bfloat162 h = __floats2bfloat162_rn(x, y);
    hi = *reinterpret_cast<uint32_t*>(&h);
    __nv_bfloat162 l = __floats2bfloat162_rn(x - __bfloat162float(h.x),
                                             y - __bfloat162float(h.y));
    lo = *reinterpret_cast<uint32_t*>(&l);
}

// ---------------------------------------------------------------------------
// Kernel 1: fused QKV projection -> bf16 hi/lo split operands.  (UNCHANGED)
// ---------------------------------------------------------------------------
__global__ __launch_bounds__(256) void proj_kernel(
    const float* __restrict__ X,
    const float* __restrict__ Wq, const float* __restrict__ bq,
    const float* __restrict__ Wk, const float* __restrict__ bk,
    const float* __restrict__ Wv, const float* __restrict__ bv)
{
    __shared__ float sA[32][68];
    __shared__ float sB[32][64];
    __shared__ float sT[64][65];   // V transpose staging (tokens x channels)

    const int m0 = blockIdx.x * 64;
    const int n0 = blockIdx.y * 64;
    const int t  = threadIdx.x;
    const int tmb = (t >> 4) * 4;
    const int tnb = (t & 15) * 4;

    float2 acc2[4][2] = {};

    for (int k0 = 0; k0 < CH; k0 += 32) {
        #pragma unroll
        for (int i = 0; i < 2; i++) {
            int idx = t + i * 256;
            int m   = idx >> 3;
            int kc  = (idx & 7) * 4;
            float4 a4 = *reinterpret_cast<const float4*>(
                &X[(size_t)(m0 + m) * CH + k0 + kc]);
            sA[kc + 0][m] = a4.x;
            sA[kc + 1][m] = a4.y;
            sA[kc + 2][m] = a4.z;
            sA[kc + 3][m] = a4.w;
        }
        #pragma unroll
        for (int i = 0; i < 8; i++) {
            int idx = t + i * 256;
            int kk  = idx >> 6;
            int nn  = idx & 63;
            int n   = n0 + nn;
            int kg  = k0 + kk;
            float v;
            if (n < 32)       v = Wq[kg * 32 + n];
            else if (n < 64)  v = Wk[kg * 32 + (n - 32)];
            else              v = Wv[kg * 256 + (n - 64)];
            sB[kk][nn] = v;
        }
        __syncthreads();

        #pragma unroll
        for (int k = 0; k < 32; k++) {
            float4 a4 = *reinterpret_cast<const float4*>(&sA[k][tmb]);
            float4 b4 = *reinterpret_cast<const float4*>(&sB[k][tnb]);
            float2 b01 = make_float2(b4.x, b4.y);
            float2 b23 = make_float2(b4.z, b4.w);
            float av[4] = {a4.x, a4.y, a4.z, a4.w};
            #pragma unroll
            for (int i = 0; i < 4; i++) {
                float2 aa = make_float2(av[i], av[i]);
                acc2[i][0] = ffma2(aa, b01, acc2[i][0]);
                acc2[i][1] = ffma2(aa, b23, acc2[i][1]);
            }
        }
        __syncthreads();
    }

    if (n0 < 64) {
        #pragma unroll
        for (int j = 0; j < 4; j++) {
            int n = n0 + tnb + j;
            float bias = (n < 32) ? bq[n] : bk[n - 32];
            #pragma unroll
            for (int i = 0; i < 4; i++) {
                int m = m0 + tmb + i;
                float val = (j & 1) ? ((j < 2) ? acc2[i][0].y : acc2[i][1].y)
                                    : ((j < 2) ? acc2[i][0].x : acc2[i][1].x);
                val += bias;
                __nv_bfloat16 h  = __float2bfloat16(val);
                __nv_bfloat16 lo = __float2bfloat16(val - __bfloat162float(h));
                if (n < 32) {
                    g_q[(size_t)m * 64 + n]      = h;
                    g_q[(size_t)m * 64 + 32 + n] = lo;
                } else {
                    int c = n - 32;
                    g_k[(size_t)m * 64 + c]      = h;
                    g_k[(size_t)m * 64 + 32 + c] = lo;
                }
            }
        }
    } else {
        #pragma unroll
        for (int j = 0; j < 4; j++) {
            int n = n0 + tnb + j;
            float bias = bv[n - 64];
            #pragma unroll
            for (int i = 0; i < 4; i++) {
                float val = (j & 1) ? ((j < 2) ? acc2[i][0].y : acc2[i][1].y)
                                    : ((j < 2) ? acc2[i][0].x : acc2[i][1].x);
                sT[tmb + i][tnb + j] = val + bias;
            }
        }
        __syncthreads();

        const int bb   = m0 >> 12;
        const int tok0 = m0 & 4095;
        const int tokg = t & 7;
        #pragma unroll
        for (int half = 0; half < 2; half++) {
            const int cl = (t >> 3) + half * 32;
            const int c  = (n0 - 64) + cl;
            uint32_t hi4[4], lo4[4];
            #pragma unroll
            for (int u = 0; u < 4; u++) {
                float v0 = sT[tokg * 8 + 2 * u][cl];
                float v1 = sT[tokg * 8 + 2 * u + 1][cl];
                bsplit(v0, v1, hi4[u], lo4[u]);
            }
            const size_t o = ((size_t)(bb * 256 + c)) * NN + tok0 + tokg * 8;
            *reinterpret_cast<uint4*>(&g_vth[o]) =
                make_uint4(hi4[0], hi4[1], hi4[2], hi4[3]);
            *reinterpret_cast<uint4*>(&g_vtl[o]) =
                make_uint4(lo4[0], lo4[1], lo4[2], lo4[3]);
        }
    }
}

// ---------------------------------------------------------------------------
// Kernel 2: flash attention via mma.sync (HMMA), FA2 layout, 16 warps.
// Warp w: qg=w>>1 (16 queries), ch=w&1 (128 channels). O = of[16][4] (64 regs).
// All fragments loaded via ldmatrix.x4 (conflict-free on 144B pitch).
// QK + exp duplicated across the 2 c-half warps of a q-group.
// ---------------------------------------------------------------------------
__global__ __launch_bounds__(ATTN_THREADS, 1) void attn_kernel(
    const float* __restrict__ X,
    const float* __restrict__ gamma_p,
    float* __restrict__ out)
{
    extern __shared__ __align__(16) char smem[];
    const int tid  = threadIdx.x;
    const int wid  = tid >> 5;
    const int lane = tid & 31;
    const int gid  = lane >> 2;   // 0..7
    const int tg   = lane & 3;    // 0..3
    const int qg   = wid >> 1;    // 0..7
    const int ch   = wid & 1;     // 0..1
    const int l7   = lane & 7;    // ldmatrix row-within-block
    const int l3   = lane >> 3;   // ldmatrix block index
    const int b    = blockIdx.x & 3;
    const int q0   = (blockIdx.x >> 2) * TQ;

    const uint32_t offK[2]  = { OFF_K0, OFF_K1 };
    const uint32_t offVH[2] = { OFF_VH0, OFF_VH1 };
    const uint32_t offVL[2] = { OFF_VL0, OFF_VL1 };

    const uint32_t sbase = smem_u32(smem);

    // per-thread ldmatrix base offsets (within a plane)
    // B-type (K rows / V rows): blocks advance along k by 8 tokens (16B)
    const uint32_t bOff = (uint32_t)(l7 * 144 + l3 * 16);
    // A-type (Q): blocks 0,1 = row-groups at k0-7; blocks 2,3 at k8-15
    const uint32_t aOff = (uint32_t)((qg * 16 + (l3 & 1) * 8 + l7) * 144 + (l3 >> 1) * 16);

    // padded-row plane loader: rows of 128B data -> 144B pitch
    auto load_pad = [&](uint32_t dstOff, const __nv_bfloat16* src,
                        int rows, size_t strideElems) {
        for (int i = tid; i < rows * 8; i += ATTN_THREADS) {
            int r = i >> 3, c = i & 7;
            cpa16(sbase + dstOff + (uint32_t)(r * 144 + c * 16),
                  src + (size_t)r * strideElems + c * 8);
        }
    };

    // ---- preload Q + tile 0, one commit group ----
    load_pad(OFF_Q,   g_q   + (size_t)(b * NN + q0) * 64, TQ, 64);
    load_pad(OFF_K0,  g_k   + (size_t)(b * NN) * 64, TK, 64);
    load_pad(OFF_VH0, g_vth + (size_t)(b * 256) * NN, 256, NN);
    load_pad(OFF_VL0, g_vtl + (size_t)(b * 256) * NN, 256, NN);
    asm volatile("cp.async.commit_group;");

    float of[16][4];
    #pragma unroll
    for (int nf = 0; nf < 16; nf++)
        #pragma unroll
        for (int e = 0; e < 4; e++) of[nf][e] = 0.f;

    float lr0 = 0.f, lr1 = 0.f;    // running row sums (rows gid, gid+8)

    for (int tt = 0; tt < NT; tt++) {
        const int cur = tt & 1;

        // prefetch tile tt+1 into the other buffer
        if (tt + 1 < NT) {
            const int j1 = (tt + 1) * TK;
            load_pad(offK[cur ^ 1],  g_k   + (size_t)(b * NN + j1) * 64, TK, 64);
            load_pad(offVH[cur ^ 1], g_vth + (size_t)(b * 256) * NN + j1, 256, NN);
            load_pad(offVL[cur ^ 1], g_vtl + (size_t)(b * 256) * NN + j1, 256, NN);
            asm volatile("cp.async.commit_group;");
            asm volatile("cp.async.wait_group 1;");
        } else {
            asm volatile("cp.async.wait_group 0;");
        }
        __syncthreads();   // tile tt visible to all warps

        // ---- Q A-fragments for this tile (ldmatrix, 144B pitch) ----
        uint32_t qh0[4], qh1[4], ql0[4], ql1[4];
        ldm_x4(sbase + OFF_Q + aOff,      qh0[0], qh0[1], qh0[2], qh0[3]);  // k 0-15
        ldm_x4(sbase + OFF_Q + aOff + 32, qh1[0], qh1[1], qh1[2], qh1[3]);  // k 16-31
        ldm_x4(sbase + OFF_Q + aOff + 64, ql0[0], ql0[1], ql0[2], ql0[3]);  // lo k 0-15
        ldm_x4(sbase + OFF_Q + aOff + 96, ql1[0], ql1[1], ql1[2], ql1[3]);  // lo k 16-31

        // ---- QK^T: S(16x64) = qh*kh + qh*kl + ql*kh ----
        float sf[8][4];
        #pragma unroll
        for (int nf = 0; nf < 8; nf++)
            #pragma unroll
            for (int e = 0; e < 4; e++) sf[nf][e] = 0.f;

        #pragma unroll
        for (int nf = 0; nf < 8; nf++) {
            const uint32_t kb = sbase + offK[cur] + (uint32_t)(nf * 8 * 144) + bOff;
            uint32_t kh[4], kl[4];
            ldm_x4(kb,      kh[0], kh[1], kh[2], kh[3]);   // hi: kc0 (b0,b1), kc1 (b0,b1)
            ldm_x4(kb + 64, kl[0], kl[1], kl[2], kl[3]);   // lo
            mma_bf16(sf[nf], qh0, kh[0], kh[1]);
            mma_bf16(sf[nf], qh1, kh[2], kh[3]);
            mma_bf16(sf[nf], qh0, kl[0], kl[1]);
            mma_bf16(sf[nf], qh1, kl[2], kl[3]);
            mma_bf16(sf[nf], ql0, kh[0], kh[1]);
            mma_bf16(sf[nf], ql1, kh[2], kh[3]);
        }

        // ---- softmax numerator + row-sum accumulation ----
        #pragma unroll
        for (int nf = 0; nf < 8; nf++) {
            sf[nf][0] = __expf(sf[nf][0]);
            sf[nf][1] = __expf(sf[nf][1]);
            sf[nf][2] = __expf(sf[nf][2]);
            sf[nf][3] = __expf(sf[nf][3]);
            lr0 += sf[nf][0] + sf[nf][1];
            lr1 += sf[nf][2] + sf[nf][3];
        }

        // ---- P -> A-fragments (hi + residual lo), S-frag identity remap ----
        uint32_t ahi[4][4], alo[4][4];
        #pragma unroll
        for (int kc = 0; kc < 4; kc++) {
            const float* p0 = sf[2 * kc];
            const float* p1 = sf[2 * kc + 1];
            bsplit(p0[0], p0[1], ahi[kc][0], alo[kc][0]);
            bsplit(p0[2], p0[3], ahi[kc][1], alo[kc][1]);
            bsplit(p1[0], p1[1], ahi[kc][2], alo[kc][2]);
            bsplit(p1[2], p1[3], ahi[kc][3], alo[kc][3]);
        }

        // ---- PV: O(16x128) += ph*vh + ph*vl + pl*vh (ldmatrix B-frags) ----
        #pragma unroll
        for (int nf = 0; nf < 16; nf++) {
            const uint32_t row = (uint32_t)((ch * 128 + nf * 8) * 144);
            const uint32_t vhB = sbase + offVH[cur] + row + bOff;
            const uint32_t vlB = sbase + offVL[cur] + row + bOff;
            uint32_t h0[4], h1[4], z0[4], z1[4];
            ldm_x4(vhB,      h0[0], h0[1], h0[2], h0[3]);  // hi, tokens 0-31 (kc0,kc1)
            ldm_x4(vhB + 64, h1[0], h1[1], h1[2], h1[3]);  // hi, tokens 32-63 (kc2,kc3)
            ldm_x4(vlB,      z0[0], z0[1], z0[2], z0[3]);  // lo, tokens 0-31
            ldm_x4(vlB + 64, z1[0], z1[1], z1[2], z1[3]);  // lo, tokens 32-63
            mma_bf16(of[nf], ahi[0], h0[0], h0[1]);
            mma_bf16(of[nf], ahi[1], h0[2], h0[3]);
            mma_bf16(of[nf], ahi[2], h1[0], h1[1]);
            mma_bf16(of[nf], ahi[3], h1[2], h1[3]);
            mma_bf16(of[nf], ahi[0], z0[0], z0[1]);
            mma_bf16(of[nf], ahi[1], z0[2], z0[3]);
            mma_bf16(of[nf], ahi[2], z1[0], z1[1]);
            mma_bf16(of[nf], ahi[3], z1[2], z1[3]);
            mma_bf16(of[nf], alo[0], h0[0], h0[1]);
            mma_bf16(of[nf], alo[1], h0[2], h0[3]);
            mma_bf16(of[nf], alo[2], h1[0], h1[1]);
            mma_bf16(of[nf], alo[3], h1[2], h1[3]);
        }
        __syncthreads();   // all warps done with buffer cur -> safe to refill
    }

    // ---- epilogue: out = gamma * O / l + X ----
    lr0 += __shfl_xor_sync(0xffffffffu, lr0, 1);
    lr0 += __shfl_xor_sync(0xffffffffu, lr0, 2);
    lr1 += __shfl_xor_sync(0xffffffffu, lr1, 1);
    lr1 += __shfl_xor_sync(0xffffffffu, lr1, 2);

    const float gm = *gamma_p;
    const float s0 = gm / lr0;
    const float s1 = gm / lr1;

    const int qa = q0 + qg * 16 + gid;
    const size_t ra = (size_t)(b * NN + qa) * CH;
    const size_t rb = ra + (size_t)8 * CH;

    #pragma unroll
    for (int nf = 0; nf < 16; nf++) {
        const int c = ch * 128 + nf * 8 + 2 * tg;
        float2 xa = *reinterpret_cast<const float2*>(&X[ra + c]);
        float2 xb = *reinterpret_cast<const float2*>(&X[rb + c]);
        float2 oa, ob;
        oa.x = fmaf(of[nf][0], s0, xa.x);
        oa.y = fmaf(of[nf][1], s0, xa.y);
        ob.x = fmaf(of[nf][2], s1, xb.x);
        ob.y = fmaf(of[nf][3], s1, xb.y);
        *reinterpret_cast<float2*>(&out[ra + c]) = oa;
        *reinterpret_cast<float2*>(&out[rb + c]) = ob;
    }
}

// ---------------------------------------------------------------------------
// Launch
// ---------------------------------------------------------------------------
extern "C" void kernel_launch(void* const* d_in, const int* in_sizes, int n_in,
                              void* d_out, int out_size)
{
    const float* X     = (const float*)d_in[0];
    const float* Wq    = (const float*)d_in[1];
    const float* bq    = (const float*)d_in[2];
    const float* Wk    = (const float*)d_in[3];
    const float* bk    = (const float*)d_in[4];
    const float* Wv    = (const float*)d_in[5];
    const float* bv    = (const float*)d_in[6];
    const float* gamma = (const float*)d_in[7];
    float* out = (float*)d_out;

    dim3 g1((BB * NN) / 64, 320 / 64);   // (256, 5)
    proj_kernel<<<g1, 256>>>(X, Wq, bq, Wk, bk, Wv, bv);

    static bool smem_cfgd = false;
    if (!smem_cfgd) {
        (void)cudaFuncSetAttribute(attn_kernel,
                                   cudaFuncAttributeMaxDynamicSharedMemorySize,
                                   (int)SMEM_TOTAL);
        smem_cfgd = true;
    }
    dim3 g2((NN / TQ) * BB, 1);          // 128 CTAs: blockIdx.x = qtile*4 + b
    attn_kernel<<<g2, ATTN_THREADS, SMEM_TOTAL>>>(X, gamma, out);
}

// round 16
// speedup vs baseline: 1.0682x; 1.0682x over previous
#include <cuda_runtime.h>
#include <cuda_bf16.h>
#include <math_constants.h>
#include <cstdint>

// Problem constants
constexpr int BB = 4;      // batch
constexpr int NN = 4096;   // H*W tokens
constexpr int CH = 256;    // channels

// Attention tiling
constexpr int TQ = 128;    // queries per CTA (8 warps x 16)
constexpr int TK = 64;     // keys per tile
constexpr int NT = NN / TK;

// ---- device scratch (bf16 hi/lo split operands) ----
__device__ __nv_bfloat16 g_q[(size_t)BB * NN * 64];     // [token][qh(32)|ql(32)]
__device__ __nv_bfloat16 g_k[(size_t)BB * NN * 64];     // [token][kh(32)|kl(32)]
__device__ __nv_bfloat16 g_vth[(size_t)BB * 256 * NN];  // [b][channel][token] V hi (transposed)
__device__ __nv_bfloat16 g_vtl[(size_t)BB * 256 * NN];  // V lo (transposed)

// ---- attn smem layout (bytes). ALL planes 144B pitch (ldmatrix conflict-free) ----
constexpr uint32_t OFF_Q   = 0;                    // 128 x 144 = 18432
constexpr uint32_t OFF_K0  = 18432;                // 64 x 144 = 9216
constexpr uint32_t OFF_K1  = OFF_K0 + 9216;
constexpr uint32_t OFF_VH0 = OFF_K1 + 9216;        // 256 x 144 = 36864
constexpr uint32_t OFF_VL0 = OFF_VH0 + 36864;
constexpr uint32_t OFF_VH1 = OFF_VL0 + 36864;
constexpr uint32_t OFF_VL1 = OFF_VH1 + 36864;
constexpr uint32_t SMEM_TOTAL = OFF_VL1 + 36864;   // 184320 B

// ---------------------------------------------------------------------------
// helpers
// ---------------------------------------------------------------------------
union F2U { float2 f; unsigned long long u; };
__device__ __forceinline__ float2 ffma2(float2 a, float2 b, float2 c) {
    F2U A, B, C, D;
    A.f = a; B.f = b; C.f = c;
    asm("fma.rn.f32x2 %0, %1, %2, %3;" : "=l"(D.u) : "l"(A.u), "l"(B.u), "l"(C.u));
    return D.f;
}

__device__ __forceinline__ uint32_t smem_u32(const void* p) {
    return (uint32_t)__cvta_generic_to_shared(const_cast<void*>(p));
}
__device__ __forceinline__ void cpa16(uint32_t dst, const void* src) {
    asm volatile("cp.async.cg.shared.global [%0], [%1], 16;" :: "r"(dst), "l"(src));
}

// mma.sync m16n8k16 row.col bf16 -> f32 accumulate (base sm_80+ PTX)
__device__ __forceinline__ void mma_bf16(float d[4], const uint32_t a[4],
                                         uint32_t b0, uint32_t b1) {
    asm volatile(
        "mma.sync.aligned.m16n8k16.row.col.f32.bf16.bf16.f32 "
        "{%0,%1,%2,%3}, {%4,%5,%6,%7}, {%8,%9}, {%0,%1,%2,%3};"
        : "+f"(d[0]), "+f"(d[1]), "+f"(d[2]), "+f"(d[3])
        : "r"(a[0]), "r"(a[1]), "r"(a[2]), "r"(a[3]), "r"(b0), "r"(b1));
}

// ldmatrix: 4x 8x8 b16 blocks, one per 8-lane address group
__device__ __forceinline__ void ldm_x4(uint32_t addr, uint32_t& r0, uint32_t& r1,
                                       uint32_t& r2, uint32_t& r3) {
    asm volatile("ldmatrix.sync.aligned.m8n8.x4.shared.b16 {%0,%1,%2,%3}, [%4];"
                 : "=r"(r0), "=r"(r1), "=r"(r2), "=r"(r3) : "r"(addr));
}

// split (x, y) into bf16x2 hi + bf16x2 residual-lo
__device__ __forceinline__ void bsplit(float x, float y, uint32_t& hi, uint32_t& lo) {
    __nv_bfloat162 h = __floats2bfloat162_rn(x, y);
    hi = *reinterpret_cast<uint32_t*>(&h);
    __nv_bfloat162 l = __floats2bfloat162_rn(x - __bfloat162float(h.x),
                                             y - __bfloat162float(h.y));
    lo = *reinterpret_cast<uint32_t*>(&l);
}

// ---------------------------------------------------------------------------
// Kernel 1: fused QKV projection -> bf16 hi/lo split operands.  (UNCHANGED)
// ---------------------------------------------------------------------------
__global__ __launch_bounds__(256) void proj_kernel(
    const float* __restrict__ X,
    const float* __restrict__ Wq, const float* __restrict__ bq,
    const float* __restrict__ Wk, const float* __restrict__ bk,
    const float* __restrict__ Wv, const float* __restrict__ bv)
{
    __shared__ float sA[32][68];
    __shared__ float sB[32][64];
    __shared__ float sT[64][65];   // V transpose staging (tokens x channels)

    const int m0 = blockIdx.x * 64;
    const int n0 = blockIdx.y * 64;
    const int t  = threadIdx.x;
    const int tmb = (t >> 4) * 4;
    const int tnb = (t & 15) * 4;

    float2 acc2[4][2] = {};

    for (int k0 = 0; k0 < CH; k0 += 32) {
        #pragma unroll
        for (int i = 0; i < 2; i++) {
            int idx = t + i * 256;
            int m   = idx >> 3;
            int kc  = (idx & 7) * 4;
            float4 a4 = *reinterpret_cast<const float4*>(
                &X[(size_t)(m0 + m) * CH + k0 + kc]);
            sA[kc + 0][m] = a4.x;
            sA[kc + 1][m] = a4.y;
            sA[kc + 2][m] = a4.z;
            sA[kc + 3][m] = a4.w;
        }
        #pragma unroll
        for (int i = 0; i < 8; i++) {
            int idx = t + i * 256;
            int kk  = idx >> 6;
            int nn  = idx & 63;
            int n   = n0 + nn;
            int kg  = k0 + kk;
            float v;
            if (n < 32)       v = Wq[kg * 32 + n];
            else if (n < 64)  v = Wk[kg * 32 + (n - 32)];
            else              v = Wv[kg * 256 + (n - 64)];
            sB[kk][nn] = v;
        }
        __syncthreads();

        #pragma unroll
        for (int k = 0; k < 32; k++) {
            float4 a4 = *reinterpret_cast<const float4*>(&sA[k][tmb]);
            float4 b4 = *reinterpret_cast<const float4*>(&sB[k][tnb]);
            float2 b01 = make_float2(b4.x, b4.y);
            float2 b23 = make_float2(b4.z, b4.w);
            float av[4] = {a4.x, a4.y, a4.z, a4.w};
            #pragma unroll
            for (int i = 0; i < 4; i++) {
                float2 aa = make_float2(av[i], av[i]);
                acc2[i][0] = ffma2(aa, b01, acc2[i][0]);
                acc2[i][1] = ffma2(aa, b23, acc2[i][1]);
            }
        }
        __syncthreads();
    }

    if (n0 < 64) {
        #pragma unroll
        for (int j = 0; j < 4; j++) {
            int n = n0 + tnb + j;
            float bias = (n < 32) ? bq[n] : bk[n - 32];
            #pragma unroll
            for (int i = 0; i < 4; i++) {
                int m = m0 + tmb + i;
                float val = (j & 1) ? ((j < 2) ? acc2[i][0].y : acc2[i][1].y)
                                    : ((j < 2) ? acc2[i][0].x : acc2[i][1].x);
                val += bias;
                __nv_bfloat16 h  = __float2bfloat16(val);
                __nv_bfloat16 lo = __float2bfloat16(val - __bfloat162float(h));
                if (n < 32) {
                    g_q[(size_t)m * 64 + n]      = h;
                    g_q[(size_t)m * 64 + 32 + n] = lo;
                } else {
                    int c = n - 32;
                    g_k[(size_t)m * 64 + c]      = h;
                    g_k[(size_t)m * 64 + 32 + c] = lo;
                }
            }
        }
    } else {
        #pragma unroll
        for (int j = 0; j < 4; j++) {
            int n = n0 + tnb + j;
            float bias = bv[n - 64];
            #pragma unroll
            for (int i = 0; i < 4; i++) {
                float val = (j & 1) ? ((j < 2) ? acc2[i][0].y : acc2[i][1].y)
                                    : ((j < 2) ? acc2[i][0].x : acc2[i][1].x);
                sT[tmb + i][tnb + j] = val + bias;
            }
        }
        __syncthreads();

        const int bb   = m0 >> 12;
        const int tok0 = m0 & 4095;
        const int tokg = t & 7;
        #pragma unroll
        for (int half = 0; half < 2; half++) {
            const int cl = (t >> 3) + half * 32;
            const int c  = (n0 - 64) + cl;
            uint32_t hi4[4], lo4[4];
            #pragma unroll
            for (int u = 0; u < 4; u++) {
                float v0 = sT[tokg * 8 + 2 * u][cl];
                float v1 = sT[tokg * 8 + 2 * u + 1][cl];
                bsplit(v0, v1, hi4[u], lo4[u]);
            }
            const size_t o = ((size_t)(bb * 256 + c)) * NN + tok0 + tokg * 8;
            *reinterpret_cast<uint4*>(&g_vth[o]) =
                make_uint4(hi4[0], hi4[1], hi4[2], hi4[3]);
            *reinterpret_cast<uint4*>(&g_vtl[o]) =
                make_uint4(lo4[0], lo4[1], lo4[2], lo4[3]);
        }
    }
}

// ---------------------------------------------------------------------------
// Kernel 2: flash attention via mma.sync (HMMA), FA2 layout, 8 warps.
// Warp = 16 queries x 256 channels (of[32][4], regs ~255, no spills).
// All fragments via ldmatrix.x4 on 144B-pitch planes (conflict-free).
// This is R13's winning layout + R14's ldmatrix loads, WITHOUT the c-split.
// ---------------------------------------------------------------------------
__global__ __launch_bounds__(256, 1) void attn_kernel(
    const float* __restrict__ X,
    const float* __restrict__ gamma_p,
    float* __restrict__ out)
{
    extern __shared__ __align__(16) char smem[];
    const int tid  = threadIdx.x;
    const int wid  = tid >> 5;
    const int lane = tid & 31;
    const int gid  = lane >> 2;   // 0..7
    const int tg   = lane & 3;    // 0..3
    const int l7   = lane & 7;    // ldmatrix row-within-block
    const int l3   = lane >> 3;   // ldmatrix block index
    const int b    = blockIdx.x & 3;
    const int q0   = (blockIdx.x >> 2) * TQ;

    const uint32_t offK[2]  = { OFF_K0, OFF_K1 };
    const uint32_t offVH[2] = { OFF_VH0, OFF_VH1 };
    const uint32_t offVL[2] = { OFF_VL0, OFF_VL1 };

    const uint32_t sbase = smem_u32(smem);

    // per-thread ldmatrix base offsets (within a plane)
    // B-type (K rows / V rows): blocks advance along k by 8 tokens (16B)
    const uint32_t bOff = (uint32_t)(l7 * 144 + l3 * 16);
    // A-type (Q): blocks 0,1 = row-groups at k0-7; blocks 2,3 at k8-15
    const uint32_t aOff = (uint32_t)((wid * 16 + (l3 & 1) * 8 + l7) * 144 + (l3 >> 1) * 16);

    // padded-row plane loader: rows of 128B data -> 144B pitch
    auto load_pad = [&](uint32_t dstOff, const __nv_bfloat16* src,
                        int rows, size_t strideElems) {
        for (int i = tid; i < rows * 8; i += 256) {
            int r = i >> 3, c = i & 7;
            cpa16(sbase + dstOff + (uint32_t)(r * 144 + c * 16),
                  src + (size_t)r * strideElems + c * 8);
        }
    };

    // ---- preload Q + tile 0, one commit group ----
    load_pad(OFF_Q,   g_q   + (size_t)(b * NN + q0) * 64, TQ, 64);
    load_pad(OFF_K0,  g_k   + (size_t)(b * NN) * 64, TK, 64);
    load_pad(OFF_VH0, g_vth + (size_t)(b * 256) * NN, 256, NN);
    load_pad(OFF_VL0, g_vtl + (size_t)(b * 256) * NN, 256, NN);
    asm volatile("cp.async.commit_group;");

    float of[32][4];
    #pragma unroll
    for (int nf = 0; nf < 32; nf++)
        #pragma unroll
        for (int e = 0; e < 4; e++) of[nf][e] = 0.f;

    uint32_t qh0[4], qh1[4], ql0[4], ql1[4];   // Q A-frags (loaded at tile 0)
    float lr0 = 0.f, lr1 = 0.f;                // running row sums (rows gid, gid+8)

    for (int tt = 0; tt < NT; tt++) {
        const int cur = tt & 1;

        // prefetch tile tt+1 into the other buffer
        if (tt + 1 < NT) {
            const int j1 = (tt + 1) * TK;
            load_pad(offK[cur ^ 1],  g_k   + (size_t)(b * NN + j1) * 64, TK, 64);
            load_pad(offVH[cur ^ 1], g_vth + (size_t)(b * 256) * NN + j1, 256, NN);
            load_pad(offVL[cur ^ 1], g_vtl + (size_t)(b * 256) * NN + j1, 256, NN);
            asm volatile("cp.async.commit_group;");
            asm volatile("cp.async.wait_group 1;");
        } else {
            asm volatile("cp.async.wait_group 0;");
        }
        __syncthreads();   // tile tt visible to all warps

        if (tt == 0) {
            // Q A-fragments once (ldmatrix, 144B pitch)
            ldm_x4(sbase + OFF_Q + aOff,      qh0[0], qh0[1], qh0[2], qh0[3]);  // hi k0-15
            ldm_x4(sbase + OFF_Q + aOff + 32, qh1[0], qh1[1], qh1[2], qh1[3]);  // hi k16-31
            ldm_x4(sbase + OFF_Q + aOff + 64, ql0[0], ql0[1], ql0[2], ql0[3]);  // lo k0-15
            ldm_x4(sbase + OFF_Q + aOff + 96, ql1[0], ql1[1], ql1[2], ql1[3]);  // lo k16-31
        }

        // ---- QK^T: S(16x64) = qh*kh + qh*kl + ql*kh ----
        float sf[8][4];
        #pragma unroll
        for (int nf = 0; nf < 8; nf++)
            #pragma unroll
            for (int e = 0; e < 4; e++) sf[nf][e] = 0.f;

        #pragma unroll
        for (int nf = 0; nf < 8; nf++) {
            const uint32_t kb = sbase + offK[cur] + (uint32_t)(nf * 8 * 144) + bOff;
            uint32_t kh[4], kl[4];
            ldm_x4(kb,      kh[0], kh[1], kh[2], kh[3]);   // hi: kc0(b0,b1), kc1(b0,b1)
            ldm_x4(kb + 64, kl[0], kl[1], kl[2], kl[3]);   // lo
            mma_bf16(sf[nf], qh0, kh[0], kh[1]);
            mma_bf16(sf[nf], qh1, kh[2], kh[3]);
            mma_bf16(sf[nf], qh0, kl[0], kl[1]);
            mma_bf16(sf[nf], qh1, kl[2], kl[3]);
            mma_bf16(sf[nf], ql0, kh[0], kh[1]);
            mma_bf16(sf[nf], ql1, kh[2], kh[3]);
        }

        // ---- softmax numerator + row-sum accumulation ----
        #pragma unroll
        for (int nf = 0; nf < 8; nf++) {
            sf[nf][0] = __expf(sf[nf][0]);
            sf[nf][1] = __expf(sf[nf][1]);
            sf[nf][2] = __expf(sf[nf][2]);
            sf[nf][3] = __expf(sf[nf][3]);
            lr0 += sf[nf][0] + sf[nf][1];
            lr1 += sf[nf][2] + sf[nf][3];
        }

        // ---- P -> A-fragments (hi + residual lo), S-frag identity remap ----
        uint32_t ahi[4][4], alo[4][4];
        #pragma unroll
        for (int kc = 0; kc < 4; kc++) {
            const float* p0 = sf[2 * kc];
            const float* p1 = sf[2 * kc + 1];
            bsplit(p0[0], p0[1], ahi[kc][0], alo[kc][0]);
            bsplit(p0[2], p0[3], ahi[kc][1], alo[kc][1]);
            bsplit(p1[0], p1[1], ahi[kc][2], alo[kc][2]);
            bsplit(p1[2], p1[3], ahi[kc][3], alo[kc][3]);
        }

        // ---- PV: O(16x256) += ph*vh + ph*vl + pl*vh (ldmatrix B-frags) ----
        #pragma unroll
        for (int nf = 0; nf < 32; nf++) {
            const uint32_t row = (uint32_t)(nf * 8 * 144);
            const uint32_t vhB = sbase + offVH[cur] + row + bOff;
            const uint32_t vlB = sbase + offVL[cur] + row + bOff;
            uint32_t h0[4], h1[4], z0[4], z1[4];
            ldm_x4(vhB,      h0[0], h0[1], h0[2], h0[3]);  // hi, tokens 0-31 (kc0,kc1)
            ldm_x4(vhB + 64, h1[0], h1[1], h1[2], h1[3]);  // hi, tokens 32-63 (kc2,kc3)
            ldm_x4(vlB,      z0[0], z0[1], z0[2], z0[3]);  // lo, tokens 0-31
            ldm_x4(vlB + 64, z1[0], z1[1], z1[2], z1[3]);  // lo, tokens 32-63
            mma_bf16(of[nf], ahi[0], h0[0], h0[1]);
            mma_bf16(of[nf], ahi[1], h0[2], h0[3]);
            mma_bf16(of[nf], ahi[2], h1[0], h1[1]);
            mma_bf16(of[nf], ahi[3], h1[2], h1[3]);
            mma_bf16(of[nf], ahi[0], z0[0], z0[1]);
            mma_bf16(of[nf], ahi[1], z0[2], z0[3]);
            mma_bf16(of[nf], ahi[2], z1[0], z1[1]);
            mma_bf16(of[nf], ahi[3], z1[2], z1[3]);
            mma_bf16(of[nf], alo[0], h0[0], h0[1]);
            mma_bf16(of[nf], alo[1], h0[2], h0[3]);
            mma_bf16(of[nf], alo[2], h1[0], h1[1]);
            mma_bf16(of[nf], alo[3], h1[2], h1[3]);
        }
        __syncthreads();   // all warps done with buffer cur -> safe to refill
    }

    // ---- epilogue: out = gamma * O / l + X ----
    lr0 += __shfl_xor_sync(0xffffffffu, lr0, 1);
    lr0 += __shfl_xor_sync(0xffffffffu, lr0, 2);
    lr1 += __shfl_xor_sync(0xffffffffu, lr1, 1);
    lr1 += __shfl_xor_sync(0xffffffffu, lr1, 2);

    const float gm = *gamma_p;
    const float s0 = gm / lr0;
    const float s1 = gm / lr1;

    const int qa = q0 + wid * 16 + gid;
    const size_t ra = (size_t)(b * NN + qa) * CH;
    const size_t rb = ra + (size_t)8 * CH;

    #pragma unroll
    for (int nf = 0; nf < 32; nf++) {
        const int c = nf * 8 + 2 * tg;
        float2 xa = *reinterpret_cast<const float2*>(&X[ra + c]);
        float2 xb = *reinterpret_cast<const float2*>(&X[rb + c]);
        float2 oa, ob;
        oa.x = fmaf(of[nf][0], s0, xa.x);
        oa.y = fmaf(of[nf][1], s0, xa.y);
        ob.x = fmaf(of[nf][2], s1, xb.x);
        ob.y = fmaf(of[nf][3], s1, xb.y);
        *reinterpret_cast<float2*>(&out[ra + c]) = oa;
        *reinterpret_cast<float2*>(&out[rb + c]) = ob;
    }
}

// ---------------------------------------------------------------------------
// Launch
// ---------------------------------------------------------------------------
extern "C" void kernel_launch(void* const* d_in, const int* in_sizes, int n_in,
                              void* d_out, int out_size)
{
    const float* X     = (const float*)d_in[0];
    const float* Wq    = (const float*)d_in[1];
    const float* bq    = (const float*)d_in[2];
    const float* Wk    = (const float*)d_in[3];
    const float* bk    = (const float*)d_in[4];
    const float* Wv    = (const float*)d_in[5];
    const float* bv    = (const float*)d_in[6];
    const float* gamma = (const float*)d_in[7];
    float* out = (float*)d_out;

    dim3 g1((BB * NN) / 64, 320 / 64);   // (256, 5)
    proj_kernel<<<g1, 256>>>(X, Wq, bq, Wk, bk, Wv, bv);

    static bool smem_cfgd = false;
    if (!smem_cfgd) {
        (void)cudaFuncSetAttribute(attn_kernel,
                                   cudaFuncAttributeMaxDynamicSharedMemorySize,
                                   (int)SMEM_TOTAL);
        smem_cfgd = true;
    }
    dim3 g2((NN / TQ) * BB, 1);          // 128 CTAs: blockIdx.x = qtile*4 + b
    attn_kernel<<<g2, 256, SMEM_TOTAL>>>(X, gamma, out);
}